// round 15
// baseline (speedup 1.0000x reference)
#include <cuda_runtime.h>
#include <cuda_fp16.h>
#include <cstdint>

#define BATCH   2
#define T_SEQ   2048
#define C_EMB   1024
#define NHEAD   16
#define HDIM    64
#define BT      (BATCH * T_SEQ)      // 4096
#define C3      (3 * C_EMB)          // 3072

// 0.125 * log2(e)
#define SCALE2  0.18033688011112043f

// ---------------- scratch (device globals) ----------------
__device__ __half g_qkv[(size_t)BT * C3];                       // q,k used; v region unused
__device__ __half g_vt[(size_t)BATCH * NHEAD * HDIM * T_SEQ];   // V^T (written by gemm1)
__device__ __half g_a[(size_t)BT * C_EMB];                      // activation (x, then y)
__device__ __half g_b[(size_t)C3 * C_EMB];                      // W_attn^T fp16
__device__ __half g_b2[(size_t)C_EMB * C_EMB];                  // W_proj^T fp16

// ---------------- PTX helpers (base-target sm_80+ only) ----------------
static __device__ __forceinline__ uint32_t smem_u32(const void* p) {
    uint32_t a;
    asm("{ .reg .u64 t; cvta.to.shared.u64 t, %1; cvt.u32.u64 %0, t; }" : "=r"(a) : "l"(p));
    return a;
}
static __device__ __forceinline__ void cp_async16(uint32_t dst, const void* src) {
    asm volatile("cp.async.cg.shared.global [%0], [%1], 16;" :: "r"(dst), "l"(src) : "memory");
}
static __device__ __forceinline__ void cp_commit() {
    asm volatile("cp.async.commit_group;" ::: "memory");
}
static __device__ __forceinline__ void cp_wait1() {
    asm volatile("cp.async.wait_group 1;" ::: "memory");
}
static __device__ __forceinline__ void cp_wait2() {
    asm volatile("cp.async.wait_group 2;" ::: "memory");
}
static __device__ __forceinline__ void ldsm_x4(uint32_t& r0, uint32_t& r1, uint32_t& r2,
                                               uint32_t& r3, uint32_t addr) {
    asm volatile("ldmatrix.sync.aligned.m8n8.x4.shared.b16 {%0,%1,%2,%3}, [%4];"
                 : "=r"(r0), "=r"(r1), "=r"(r2), "=r"(r3) : "r"(addr));
}
static __device__ __forceinline__ void mma_f16(float* d, const uint32_t* a,
                                               uint32_t b0, uint32_t b1) {
    asm volatile(
        "mma.sync.aligned.m16n8k16.row.col.f32.f16.f16.f32 "
        "{%0,%1,%2,%3}, {%4,%5,%6,%7}, {%8,%9}, {%0,%1,%2,%3};"
        : "+f"(d[0]), "+f"(d[1]), "+f"(d[2]), "+f"(d[3])
        : "r"(a[0]), "r"(a[1]), "r"(a[2]), "r"(a[3]), "r"(b0), "r"(b1));
}
static __device__ __forceinline__ float ex2f(float x) {
    float r;
    asm("ex2.approx.f32 %0, %1;" : "=f"(r) : "f"(x));
    return r;
}
static __device__ __forceinline__ uint32_t ex2h2(__half2 x) {
    uint32_t r;
    uint32_t xi = *reinterpret_cast<uint32_t*>(&x);
    asm("ex2.approx.f16x2 %0, %1;" : "=r"(r) : "r"(xi));
    return r;
}
static __device__ __forceinline__ uint32_t sw128(uint32_t o) {
    return o ^ ((o >> 3) & 0x70);
}

// ---------------- HMMA GEMM: C = A @ B^T + bias (single fp16) ----------------
// CTA 128x128, 4 warps (2Mx2N, warp tile 64x64), BK=64, 3-stage, 2 CTAs/SM.
// Per k16-step: 8 ldsm -> 32 MMA (ratio 4.0 vs prior 2.67).
// VSPLIT (gemm1): N-blocks >= 2*C_EMB (V third) written transposed into vt.
#define GBM 128
#define GBN 128
#define GBK 64
#define G_STG 32768
#define SM_TOTAL (3 * G_STG)

template <bool HALF_OUT, bool VSPLIT>
__global__ __launch_bounds__(128, 2)
void gemm_f16(const __half* __restrict__ A, const __half* __restrict__ B,
              const float* __restrict__ bias, float* __restrict__ C,
              __half* __restrict__ Ch, __half* __restrict__ vt,
              int M, int N, int K)
{
    extern __shared__ char smem[];
    const uint32_t sbase = smem_u32(smem);
    const int t = threadIdx.x, lane = t & 31, w = t >> 5;   // 4 warps
    const int wm = (w >> 1) * 64;
    const int wn = (w & 1) * 64;
    const int bm = blockIdx.y * GBM, bn = blockIdx.x * GBN;

    const int lr = t >> 3;          // 0..15
    const int lc = (t & 7) * 16;
    const size_t Kb = (size_t)K * 2;
    const char* pA = (const char*)A + (size_t)(bm + lr) * Kb + lc;
    const char* pB = (const char*)B + (size_t)(bn + lr) * Kb + lc;

    auto issue = [&](int c) {
        const uint32_t sb = sbase + (c % 3) * G_STG;
        const size_t go = (size_t)c * 128;
        #pragma unroll
        for (int rr = 0; rr < 8; rr++) {
            uint32_t so = sw128((uint32_t)(lr + rr * 16) * 128 + lc);
            size_t gr = (size_t)rr * 16 * Kb + go;
            cp_async16(sb + so,         pA + gr);
            cp_async16(sb + 16384 + so, pB + gr);
        }
    };

    float acc[4][8][4] = {};
    const int nc = K / GBK;

    issue(0); cp_commit();
    issue(1); cp_commit();
    issue(2); cp_commit();

    const int frow = lane & 15;
    const int fcol = (lane >> 4) * 16;

    for (int c = 0; c < nc; c++) {
        cp_wait2();
        __syncthreads();
        const uint32_t sb = sbase + (c % 3) * G_STG;

        #pragma unroll
        for (int ks = 0; ks < GBK / 16; ks++) {
            const int kb = ks * 32 + fcol;
            uint32_t af[4][4];
            #pragma unroll
            for (int mt = 0; mt < 4; mt++) {
                uint32_t o = sw128((uint32_t)(wm + mt * 16 + frow) * 128 + kb);
                ldsm_x4(af[mt][0], af[mt][1], af[mt][2], af[mt][3], sb + o);
            }
            uint32_t bf[4][4];
            #pragma unroll
            for (int nt = 0; nt < 4; nt++) {
                uint32_t o = sw128((uint32_t)(wn + nt * 16 + frow) * 128 + kb);
                ldsm_x4(bf[nt][0], bf[nt][1], bf[nt][2], bf[nt][3], sb + 16384 + o);
            }
            #pragma unroll
            for (int nt = 0; nt < 4; nt++)
                #pragma unroll
                for (int mt = 0; mt < 4; mt++)
                    #pragma unroll
                    for (int hf = 0; hf < 2; hf++)
                        mma_f16(acc[mt][nt * 2 + hf], af[mt], bf[nt][hf], bf[nt][hf + 2]);
        }
        __syncthreads();
        if (c + 3 < nc) issue(c + 3);
        cp_commit();
    }

    const int g = lane >> 2, tc = lane & 3;
    const bool isV = VSPLIT && (bn >= 2 * C_EMB);
    #pragma unroll
    for (int mt = 0; mt < 4; mt++) {
        const int row0 = bm + wm + mt * 16 + g;
        #pragma unroll
        for (int j = 0; j < 8; j++) {
            const int col = bn + wn + j * 8 + tc * 2;
            float b0 = bias[col], b1 = bias[col + 1];
            float* d = acc[mt][j];
            float v00 = d[0] + b0, v01 = d[1] + b1;
            float v10 = d[2] + b0, v11 = d[3] + b1;
            if constexpr (VSPLIT) {
                if (isV) {
                    const int vcol = col - 2 * C_EMB;
                    const int hh = vcol >> 6, dd = vcol & 63;
                    const int bb = row0 >> 11, tt = row0 & 2047;
                    size_t base = ((size_t)(bb * NHEAD + hh) * HDIM + dd) * T_SEQ + tt;
                    vt[base]             = __float2half(v00);
                    vt[base + T_SEQ]     = __float2half(v01);
                    vt[base + 8]         = __float2half(v10);
                    vt[base + T_SEQ + 8] = __float2half(v11);
                    continue;
                }
            }
            if constexpr (HALF_OUT) {
                *(__half2*)(Ch + (size_t)row0 * N + col) = __floats2half2_rn(v00, v01);
                *(__half2*)(Ch + (size_t)(row0 + 8) * N + col) = __floats2half2_rn(v10, v11);
            } else {
                *(float2*)(C + (size_t)row0 * N + col) = make_float2(v00, v01);
                *(float2*)(C + (size_t)(row0 + 8) * N + col) = make_float2(v10, v11);
            }
        }
    }
}

// ---------------- merged conversion kernel ----------------
__global__ void conv_all(const float* __restrict__ x, __half* __restrict__ a,
                         const float* __restrict__ Wa, const float* __restrict__ Wp,
                         __half* __restrict__ ba, __half* __restrict__ bp)
{
    __shared__ float tile[32][33];
    const int t = threadIdx.x;
    if (blockIdx.x < 4096) {
        int i = (blockIdx.x * 256 + t) * 4;
        float4 v = *(const float4*)(x + i);
        *(__half2*)(a + i)     = __floats2half2_rn(v.x, v.y);
        *(__half2*)(a + i + 2) = __floats2half2_rn(v.z, v.w);
        return;
    }
    const int bid = blockIdx.x - 4096;
    const int bxT = bid & 127;
    const int k0  = (bid >> 7) * 32;
    const float* W;
    __half* outp;
    int N, n0;
    if (bxT < 96) { W = Wa; outp = ba; N = C3;    n0 = bxT * 32; }
    else          { W = Wp; outp = bp; N = C_EMB; n0 = (bxT - 96) * 32; }
    const int tx = t & 31, ty = t >> 5;
    #pragma unroll
    for (int j = 0; j < 32; j += 8)
        tile[ty + j][tx] = W[(size_t)(k0 + ty + j) * N + n0 + tx];
    __syncthreads();
    #pragma unroll
    for (int j = 0; j < 32; j += 8)
        outp[(size_t)(n0 + ty + j) * C_EMB + k0 + tx] = __float2half(tile[tx][ty + j]);
}

// ---------------- HMMA flash attention (unchanged from R14) ----------------
#define A_SQ   0
#define A_ONES 8192
#define A_SK   10240
#define A_STG  32768
#define A_SMEM (A_SK + 2 * A_STG)   // 75776 -> 3 CTAs/SM

__global__ __launch_bounds__(128, 3)
void attn_f16(const __half* __restrict__ qkv, const __half* __restrict__ vt,
              __half* __restrict__ y)
{
    extern __shared__ char smem[];
    const uint32_t sb = smem_u32(smem);
    const int t = threadIdx.x, lane = t & 31, w = t >> 5;
    const int qb = gridDim.x - 1 - blockIdx.x;
    const int h = blockIdx.y, b = blockIdx.z;
    const int Q0 = qb * 64;
    const int nkt = (Q0 >> 7) + 1;

    const int lr = t >> 3;
    const int lc = (t & 7) * 16;
    const char* qb8 = (const char*)qkv;
    const char* vb8 = (const char*)vt;

    {
        uint32_t v = (t < 8) ? 0x3C003C00u : 0u;
        *(uint4*)(smem + A_ONES + t * 16) = make_uint4(v, v, v, v);
    }

    auto issueQ = [&]() {
        #pragma unroll
        for (int rr = 0; rr < 4; rr++) {
            int row = lr + rr * 16;
            size_t g = ((size_t)(b * T_SEQ + Q0 + row) * C3 + h * HDIM) * 2 + lc;
            cp_async16(sb + A_SQ + sw128((uint32_t)row * 128 + lc), qb8 + g);
        }
    };
    auto issueKV = [&](int kt) {
        uint32_t s0 = sb + A_SK + (kt & 1) * A_STG;
        #pragma unroll
        for (int rr = 0; rr < 8; rr++) {
            int row = lr + rr * 16;
            uint32_t so = sw128((uint32_t)row * 128 + lc);
            size_t gk = ((size_t)(b * T_SEQ + kt * 128 + row) * C3 + C_EMB + h * HDIM) * 2 + lc;
            cp_async16(s0 + so, qb8 + gk);
        }
        #pragma unroll
        for (int j = 0; j < 2; j++) {
            #pragma unroll
            for (int rr = 0; rr < 4; rr++) {
                int row = lr + rr * 16;
                uint32_t so = sw128((uint32_t)row * 128 + lc) + j * 8192;
                size_t gv = (((size_t)(b * NHEAD + h) * HDIM + row) * T_SEQ
                             + kt * 128 + j * 64) * 2 + lc;
                cp_async16(s0 + 16384 + so, vb8 + gv);
            }
        }
    };

    issueQ(); issueKV(0); cp_commit();
    if (nkt > 1) issueKV(1);
    cp_commit();

    const int frow = lane & 15;
    const int fcol = (lane >> 4) * 16;
    const int g = lane >> 2, tc = lane & 3;

    cp_wait1();
    __syncthreads();

    uint32_t qf[4][4];
    #pragma unroll
    for (int ks = 0; ks < 4; ks++) {
        uint32_t o = sw128((uint32_t)(w * 16 + frow) * 128 + ks * 32 + fcol);
        ldsm_x4(qf[ks][0], qf[ks][1], qf[ks][2], qf[ks][3], sb + A_SQ + o);
    }
    uint32_t of[4];
    ldsm_x4(of[0], of[1], of[2], of[3], sb + A_ONES + sw128((uint32_t)frow * 128 + fcol));

    float oacc[8][4] = {};
    float sumacc[4] = {};
    float mprev0 = -1e30f, mprev1 = -1e30f;
    const int r0 = Q0 + w * 16 + g;
    const int r1 = r0 + 8;

    for (int kt = 0; kt < nkt; kt++) {
        if (kt > 0) { cp_wait1(); __syncthreads(); }
        const uint32_t s0 = sb + A_SK + (kt & 1) * A_STG;
        const bool diag = (kt == nkt - 1);
        int ngmax = 8;
        if (diag) {
            ngmax = ((Q0 & 127) >> 4) + w + 1;
            if (ngmax > 8) ngmax = 8;
        }

        float s[16][4] = {};
        #pragma unroll
        for (int ng = 0; ng < 8; ng++) {
            if (ng < ngmax) {
                #pragma unroll
                for (int ks = 0; ks < 4; ks++) {
                    uint32_t o = sw128((uint32_t)(ng * 16 + frow) * 128 + ks * 32 + fcol);
                    uint32_t kh[4];
                    ldsm_x4(kh[0], kh[1], kh[2], kh[3], s0 + o);
                    #pragma unroll
                    for (int hf = 0; hf < 2; hf++)
                        mma_f16(s[ng * 2 + hf], qf[ks], kh[hf], kh[hf + 2]);
                }
            }
        }

        if (diag) {
            #pragma unroll
            for (int i = 0; i < 16; i++) {
                int kk = kt * 128 + i * 8 + tc * 2;
                if (kk     > r0) s[i][0] = -1e30f;
                if (kk + 1 > r0) s[i][1] = -1e30f;
                if (kk     > r1) s[i][2] = -1e30f;
                if (kk + 1 > r1) s[i][3] = -1e30f;
            }
        }

        float mx0 = -1e30f, mx1 = -1e30f;
        #pragma unroll
        for (int i = 0; i < 16; i++) {
            mx0 = fmaxf(mx0, fmaxf(s[i][0], s[i][1]));
            mx1 = fmaxf(mx1, fmaxf(s[i][2], s[i][3]));
        }
        mx0 = fmaxf(mx0, __shfl_xor_sync(0xffffffffu, mx0, 1));
        mx0 = fmaxf(mx0, __shfl_xor_sync(0xffffffffu, mx0, 2));
        mx1 = fmaxf(mx1, __shfl_xor_sync(0xffffffffu, mx1, 1));
        mx1 = fmaxf(mx1, __shfl_xor_sync(0xffffffffu, mx1, 2));
        float mn0 = fmaxf(mprev0, mx0 * SCALE2), mn1 = fmaxf(mprev1, mx1 * SCALE2);
        float cf0 = ex2f(mprev0 - mn0), cf1 = ex2f(mprev1 - mn1);
        mprev0 = mn0; mprev1 = mn1;

        #pragma unroll
        for (int i = 0; i < 8; i++) {
            oacc[i][0] *= cf0; oacc[i][1] *= cf0;
            oacc[i][2] *= cf1; oacc[i][3] *= cf1;
        }
        sumacc[0] *= cf0; sumacc[1] *= cf0;
        sumacc[2] *= cf1; sumacc[3] *= cf1;

        #pragma unroll
        for (int half = 0; half < 2; half++) {
            uint32_t ph2[8][2];
            #pragma unroll
            for (int ii = 0; ii < 8; ii++) {
                const int i = half * 8 + ii;
                float a0 = fmaf(s[i][0], SCALE2, -mn0);
                float a1 = fmaf(s[i][1], SCALE2, -mn0);
                float a2 = fmaf(s[i][2], SCALE2, -mn1);
                float a3 = fmaf(s[i][3], SCALE2, -mn1);
                ph2[ii][0] = ex2h2(__floats2half2_rn(a0, a1));
                ph2[ii][1] = ex2h2(__floats2half2_rn(a2, a3));
            }
            #pragma unroll
            for (int kgl = 0; kgl < 4; kgl++) {
                const int kg = half * 4 + kgl;
                if (kg < ngmax) {
                    const int h2i = kg >> 2, ks = kg & 3;
                    uint32_t ph[4] = { ph2[2 * kgl][0], ph2[2 * kgl][1],
                                       ph2[2 * kgl + 1][0], ph2[2 * kgl + 1][1] };
                    #pragma unroll
                    for (int ng = 0; ng < 4; ng++) {
                        uint32_t o = sw128((uint32_t)(ng * 16 + frow) * 128 + ks * 32 + fcol)
                                     + h2i * 8192;
                        uint32_t v4[4];
                        ldsm_x4(v4[0], v4[1], v4[2], v4[3], s0 + 16384 + o);
                        #pragma unroll
                        for (int hf = 0; hf < 2; hf++)
                            mma_f16(oacc[ng * 2 + hf], ph, v4[hf], v4[hf + 2]);
                    }
                    mma_f16(sumacc, ph, of[0], of[2]);
                }
            }
        }

        __syncthreads();
        if (kt + 2 < nkt) issueKV(kt + 2);
        cp_commit();
    }

    float sum0 = __shfl_sync(0xffffffffu, sumacc[0], lane & ~3);
    float sum1 = __shfl_sync(0xffffffffu, sumacc[2], lane & ~3);
    float inv0 = 1.f / sum0, inv1 = 1.f / sum1;
    size_t row0 = (size_t)(b * T_SEQ + Q0 + w * 16 + g);
    #pragma unroll
    for (int i = 0; i < 8; i++) {
        int col = h * HDIM + i * 8 + tc * 2;
        *(__half2*)(y + row0 * C_EMB + col) =
            __floats2half2_rn(oacc[i][0] * inv0, oacc[i][1] * inv0);
        *(__half2*)(y + (row0 + 8) * C_EMB + col) =
            __floats2half2_rn(oacc[i][2] * inv1, oacc[i][3] * inv1);
    }
}

// ---------------- launch ----------------
extern "C" void kernel_launch(void* const* d_in, const int* in_sizes, int n_in,
                              void* d_out, int out_size)
{
    const float* x      = (const float*)d_in[0];
    const float* W_attn = (const float*)d_in[1];
    const float* b_attn = (const float*)d_in[2];
    const float* W_proj = (const float*)d_in[3];
    const float* b_proj = (const float*)d_in[4];
    float* out = (float*)d_out;

    __half *qkv, *vt, *a, *bw, *bw2;
    cudaGetSymbolAddress((void**)&qkv, g_qkv);
    cudaGetSymbolAddress((void**)&vt, g_vt);
    cudaGetSymbolAddress((void**)&a, g_a);
    cudaGetSymbolAddress((void**)&bw, g_b);
    cudaGetSymbolAddress((void**)&bw2, g_b2);

    cudaFuncSetAttribute((const void*)gemm_f16<true, true>,
                         cudaFuncAttributeMaxDynamicSharedMemorySize, SM_TOTAL);
    cudaFuncSetAttribute((const void*)gemm_f16<false, false>,
                         cudaFuncAttributeMaxDynamicSharedMemorySize, SM_TOTAL);
    cudaFuncSetAttribute((const void*)attn_f16,
                         cudaFuncAttributeMaxDynamicSharedMemorySize, A_SMEM);

    conv_all<<<4096 + 128 * 32, 256>>>(x, a, W_attn, W_proj, bw, bw2);
    gemm_f16<true, true><<<dim3(C3 / GBN, BT / GBM), 128, SM_TOTAL>>>(
        a, bw, b_attn, nullptr, qkv, vt, BT, C3, C_EMB);
    attn_f16<<<dim3(T_SEQ / 64, NHEAD, BATCH), 128, A_SMEM>>>(qkv, vt, a);
    gemm_f16<false, false><<<dim3(C_EMB / GBN, BT / GBM), 128, SM_TOTAL>>>(
        a, bw2, b_proj, out, nullptr, nullptr, BT, C_EMB, C_EMB);
}

// round 16
// speedup vs baseline: 1.0119x; 1.0119x over previous
#include <cuda_runtime.h>
#include <cuda_fp16.h>
#include <cstdint>

#define BATCH   2
#define T_SEQ   2048
#define C_EMB   1024
#define NHEAD   16
#define HDIM    64
#define BT      (BATCH * T_SEQ)      // 4096
#define C3      (3 * C_EMB)          // 3072

// 0.125 * log2(e)
#define SCALE2  0.18033688011112043f

// ---------------- scratch (device globals) ----------------
__device__ __half g_qkv[(size_t)BT * C3];                       // q,k used; v region unused
__device__ __half g_vt[(size_t)BATCH * NHEAD * HDIM * T_SEQ];   // V^T (written by gemm1)
__device__ __half g_a[(size_t)BT * C_EMB];                      // activation (x, then y)
__device__ __half g_b[(size_t)C3 * C_EMB];                      // W_attn^T fp16
__device__ __half g_b2[(size_t)C_EMB * C_EMB];                  // W_proj^T fp16

// ---------------- PTX helpers (base-target sm_80+ only) ----------------
static __device__ __forceinline__ uint32_t smem_u32(const void* p) {
    uint32_t a;
    asm("{ .reg .u64 t; cvta.to.shared.u64 t, %1; cvt.u32.u64 %0, t; }" : "=r"(a) : "l"(p));
    return a;
}
static __device__ __forceinline__ void cp_async16(uint32_t dst, const void* src) {
    asm volatile("cp.async.cg.shared.global [%0], [%1], 16;" :: "r"(dst), "l"(src) : "memory");
}
static __device__ __forceinline__ void cp_commit() {
    asm volatile("cp.async.commit_group;" ::: "memory");
}
static __device__ __forceinline__ void cp_wait1() {
    asm volatile("cp.async.wait_group 1;" ::: "memory");
}
static __device__ __forceinline__ void cp_wait2() {
    asm volatile("cp.async.wait_group 2;" ::: "memory");
}
static __device__ __forceinline__ void ldsm_x4(uint32_t& r0, uint32_t& r1, uint32_t& r2,
                                               uint32_t& r3, uint32_t addr) {
    asm volatile("ldmatrix.sync.aligned.m8n8.x4.shared.b16 {%0,%1,%2,%3}, [%4];"
                 : "=r"(r0), "=r"(r1), "=r"(r2), "=r"(r3) : "r"(addr));
}
static __device__ __forceinline__ void mma_f16(float* d, const uint32_t* a,
                                               uint32_t b0, uint32_t b1) {
    asm volatile(
        "mma.sync.aligned.m16n8k16.row.col.f32.f16.f16.f32 "
        "{%0,%1,%2,%3}, {%4,%5,%6,%7}, {%8,%9}, {%0,%1,%2,%3};"
        : "+f"(d[0]), "+f"(d[1]), "+f"(d[2]), "+f"(d[3])
        : "r"(a[0]), "r"(a[1]), "r"(a[2]), "r"(a[3]), "r"(b0), "r"(b1));
}
static __device__ __forceinline__ float ex2f(float x) {
    float r;
    asm("ex2.approx.f32 %0, %1;" : "=f"(r) : "f"(x));
    return r;
}
static __device__ __forceinline__ uint32_t ex2h2(__half2 x) {
    uint32_t r;
    uint32_t xi = *reinterpret_cast<uint32_t*>(&x);
    asm("ex2.approx.f16x2 %0, %1;" : "=r"(r) : "r"(xi));
    return r;
}
static __device__ __forceinline__ uint32_t sw128(uint32_t o) {
    return o ^ ((o >> 3) & 0x70);
}

// ---------------- HMMA GEMM: C = A @ B^T + bias (single fp16) ----------------
// CTA 128x128, 8 warps (4Mx2N, warp tile 32x64), BK=64, 3-stage, 2 CTAs/SM.
// VSPLIT (gemm1): N-blocks >= 2*C_EMB (V third) written transposed into vt.
#define GBM 128
#define GBN 128
#define GBK 64
#define G_STG 32768
#define SM_TOTAL (3 * G_STG)

template <bool HALF_OUT, bool VSPLIT>
__global__ __launch_bounds__(256, 2)
void gemm_f16(const __half* __restrict__ A, const __half* __restrict__ B,
              const float* __restrict__ bias, float* __restrict__ C,
              __half* __restrict__ Ch, __half* __restrict__ vt,
              int M, int N, int K)
{
    extern __shared__ char smem[];
    const uint32_t sbase = smem_u32(smem);
    const int t = threadIdx.x, lane = t & 31, w = t >> 5;
    const int wm = (w >> 1) * 32;
    const int wn = (w & 1) * 64;
    const int bm = blockIdx.y * GBM, bn = blockIdx.x * GBN;

    const int lr = t >> 3;
    const int lc = (t & 7) * 16;
    const size_t Kb = (size_t)K * 2;
    const char* pA = (const char*)A + (size_t)(bm + lr) * Kb + lc;
    const char* pB = (const char*)B + (size_t)(bn + lr) * Kb + lc;

    auto issue = [&](int c) {
        const uint32_t sb = sbase + (c % 3) * G_STG;
        const size_t go = (size_t)c * 128;
        #pragma unroll
        for (int rr = 0; rr < 4; rr++) {
            uint32_t so = sw128((uint32_t)(lr + rr * 32) * 128 + lc);
            cp_async16(sb + so,         pA + (size_t)rr * 32 * Kb + go);
            cp_async16(sb + 16384 + so, pB + (size_t)rr * 32 * Kb + go);
        }
    };

    float acc[2][8][4] = {};
    const int nc = K / GBK;

    issue(0); cp_commit();
    issue(1); cp_commit();
    issue(2); cp_commit();

    const int frow = lane & 15;
    const int fcol = (lane >> 4) * 16;

    for (int c = 0; c < nc; c++) {
        cp_wait2();
        __syncthreads();
        const uint32_t sb = sbase + (c % 3) * G_STG;

        #pragma unroll
        for (int ks = 0; ks < GBK / 16; ks++) {
            const int kb = ks * 32 + fcol;
            uint32_t af[2][4];
            #pragma unroll
            for (int mt = 0; mt < 2; mt++) {
                uint32_t o = sw128((uint32_t)(wm + mt * 16 + frow) * 128 + kb);
                ldsm_x4(af[mt][0], af[mt][1], af[mt][2], af[mt][3], sb + o);
            }
            uint32_t bf[4][4];
            #pragma unroll
            for (int nt = 0; nt < 4; nt++) {
                uint32_t o = sw128((uint32_t)(wn + nt * 16 + frow) * 128 + kb);
                ldsm_x4(bf[nt][0], bf[nt][1], bf[nt][2], bf[nt][3], sb + 16384 + o);
            }
            #pragma unroll
            for (int nt = 0; nt < 4; nt++)
                #pragma unroll
                for (int mt = 0; mt < 2; mt++)
                    #pragma unroll
                    for (int hf = 0; hf < 2; hf++)
                        mma_f16(acc[mt][nt * 2 + hf], af[mt], bf[nt][hf], bf[nt][hf + 2]);
        }
        __syncthreads();
        if (c + 3 < nc) issue(c + 3);
        cp_commit();
    }

    const int g = lane >> 2, tc = lane & 3;
    const bool isV = VSPLIT && (bn >= 2 * C_EMB);

    // bias hoisted: col depends only on j, not mt
    float2 bv[8];
    #pragma unroll
    for (int j = 0; j < 8; j++) {
        const int col = bn + wn + j * 8 + tc * 2;
        bv[j] = make_float2(bias[col], bias[col + 1]);
    }

    #pragma unroll
    for (int mt = 0; mt < 2; mt++) {
        const int row0 = bm + wm + mt * 16 + g;
        #pragma unroll
        for (int j = 0; j < 8; j++) {
            const int col = bn + wn + j * 8 + tc * 2;
            float* d = acc[mt][j];
            float v00 = d[0] + bv[j].x, v01 = d[1] + bv[j].y;
            float v10 = d[2] + bv[j].x, v11 = d[3] + bv[j].y;
            if constexpr (VSPLIT) {
                if (isV) {
                    const int vcol = col - 2 * C_EMB;
                    const int hh = vcol >> 6, dd = vcol & 63;
                    const int bb = row0 >> 11, tt = row0 & 2047;
                    size_t base = ((size_t)(bb * NHEAD + hh) * HDIM + dd) * T_SEQ + tt;
                    vt[base]             = __float2half(v00);
                    vt[base + T_SEQ]     = __float2half(v01);
                    vt[base + 8]         = __float2half(v10);
                    vt[base + T_SEQ + 8] = __float2half(v11);
                    continue;
                }
            }
            if constexpr (HALF_OUT) {
                *(__half2*)(Ch + (size_t)row0 * N + col) = __floats2half2_rn(v00, v01);
                *(__half2*)(Ch + (size_t)(row0 + 8) * N + col) = __floats2half2_rn(v10, v11);
            } else {
                *(float2*)(C + (size_t)row0 * N + col) = make_float2(v00, v01);
                *(float2*)(C + (size_t)(row0 + 8) * N + col) = make_float2(v10, v11);
            }
        }
    }
}

// ---------------- merged conversion kernel ----------------
__global__ void conv_all(const float* __restrict__ x, __half* __restrict__ a,
                         const float* __restrict__ Wa, const float* __restrict__ Wp,
                         __half* __restrict__ ba, __half* __restrict__ bp)
{
    __shared__ float tile[32][33];
    const int t = threadIdx.x;
    if (blockIdx.x < 4096) {
        int i = (blockIdx.x * 256 + t) * 4;
        float4 v = *(const float4*)(x + i);
        *(__half2*)(a + i)     = __floats2half2_rn(v.x, v.y);
        *(__half2*)(a + i + 2) = __floats2half2_rn(v.z, v.w);
        return;
    }
    const int bid = blockIdx.x - 4096;
    const int bxT = bid & 127;
    const int k0  = (bid >> 7) * 32;
    const float* W;
    __half* outp;
    int N, n0;
    if (bxT < 96) { W = Wa; outp = ba; N = C3;    n0 = bxT * 32; }
    else          { W = Wp; outp = bp; N = C_EMB; n0 = (bxT - 96) * 32; }
    const int tx = t & 31, ty = t >> 5;
    #pragma unroll
    for (int j = 0; j < 32; j += 8)
        tile[ty + j][tx] = W[(size_t)(k0 + ty + j) * N + n0 + tx];
    __syncthreads();
    #pragma unroll
    for (int j = 0; j < 32; j += 8)
        outp[(size_t)(n0 + ty + j) * C_EMB + k0 + tx] = __float2half(tile[tx][ty + j]);
}

// ---------------- HMMA flash attention (causal), single fp16 ----------------
// CTA: 64 q rows x (b,h); 4 warps x 16 rows; 128-key tiles, 2-stage pipeline.
// P via ex2.approx.f16x2 in two halves; row-sum via tensor-core ones block.
#define A_SQ   0
#define A_ONES 8192
#define A_SK   10240
#define A_STG  32768
#define A_SMEM (A_SK + 2 * A_STG)   // 75776 -> 3 CTAs/SM

__global__ __launch_bounds__(128, 3)
void attn_f16(const __half* __restrict__ qkv, const __half* __restrict__ vt,
              __half* __restrict__ y)
{
    extern __shared__ char smem[];
    const uint32_t sb = smem_u32(smem);
    const int t = threadIdx.x, lane = t & 31, w = t >> 5;
    const int qb = gridDim.x - 1 - blockIdx.x;
    const int h = blockIdx.y, b = blockIdx.z;
    const int Q0 = qb * 64;
    const int nkt = (Q0 >> 7) + 1;

    const int lr = t >> 3;
    const int lc = (t & 7) * 16;
    const char* qb8 = (const char*)qkv;
    const char* vb8 = (const char*)vt;

    {
        uint32_t v = (t < 8) ? 0x3C003C00u : 0u;
        *(uint4*)(smem + A_ONES + t * 16) = make_uint4(v, v, v, v);
    }

    auto issueQ = [&]() {
        #pragma unroll
        for (int rr = 0; rr < 4; rr++) {
            int row = lr + rr * 16;
            size_t g = ((size_t)(b * T_SEQ + Q0 + row) * C3 + h * HDIM) * 2 + lc;
            cp_async16(sb + A_SQ + sw128((uint32_t)row * 128 + lc), qb8 + g);
        }
    };
    auto issueKV = [&](int kt) {
        uint32_t s0 = sb + A_SK + (kt & 1) * A_STG;
        #pragma unroll
        for (int rr = 0; rr < 8; rr++) {
            int row = lr + rr * 16;
            uint32_t so = sw128((uint32_t)row * 128 + lc);
            size_t gk = ((size_t)(b * T_SEQ + kt * 128 + row) * C3 + C_EMB + h * HDIM) * 2 + lc;
            cp_async16(s0 + so, qb8 + gk);
        }
        #pragma unroll
        for (int j = 0; j < 2; j++) {
            #pragma unroll
            for (int rr = 0; rr < 4; rr++) {
                int row = lr + rr * 16;
                uint32_t so = sw128((uint32_t)row * 128 + lc) + j * 8192;
                size_t gv = (((size_t)(b * NHEAD + h) * HDIM + row) * T_SEQ
                             + kt * 128 + j * 64) * 2 + lc;
                cp_async16(s0 + 16384 + so, vb8 + gv);
            }
        }
    };

    issueQ(); issueKV(0); cp_commit();
    if (nkt > 1) issueKV(1);
    cp_commit();

    const int frow = lane & 15;
    const int fcol = (lane >> 4) * 16;
    const int g = lane >> 2, tc = lane & 3;

    cp_wait1();
    __syncthreads();

    uint32_t qf[4][4];
    #pragma unroll
    for (int ks = 0; ks < 4; ks++) {
        uint32_t o = sw128((uint32_t)(w * 16 + frow) * 128 + ks * 32 + fcol);
        ldsm_x4(qf[ks][0], qf[ks][1], qf[ks][2], qf[ks][3], sb + A_SQ + o);
    }
    uint32_t of[4];
    ldsm_x4(of[0], of[1], of[2], of[3], sb + A_ONES + sw128((uint32_t)frow * 128 + fcol));

    float oacc[8][4] = {};
    float sumacc[4] = {};
    float mprev0 = -1e30f, mprev1 = -1e30f;
    const int r0 = Q0 + w * 16 + g;
    const int r1 = r0 + 8;

    for (int kt = 0; kt < nkt; kt++) {
        if (kt > 0) { cp_wait1(); __syncthreads(); }
        const uint32_t s0 = sb + A_SK + (kt & 1) * A_STG;
        const bool diag = (kt == nkt - 1);
        int ngmax = 8;
        if (diag) {
            ngmax = ((Q0 & 127) >> 4) + w + 1;
            if (ngmax > 8) ngmax = 8;
        }

        float s[16][4] = {};
        #pragma unroll
        for (int ng = 0; ng < 8; ng++) {
            if (ng < ngmax) {
                #pragma unroll
                for (int ks = 0; ks < 4; ks++) {
                    uint32_t o = sw128((uint32_t)(ng * 16 + frow) * 128 + ks * 32 + fcol);
                    uint32_t kh[4];
                    ldsm_x4(kh[0], kh[1], kh[2], kh[3], s0 + o);
                    #pragma unroll
                    for (int hf = 0; hf < 2; hf++)
                        mma_f16(s[ng * 2 + hf], qf[ks], kh[hf], kh[hf + 2]);
                }
            }
        }

        if (diag) {
            #pragma unroll
            for (int i = 0; i < 16; i++) {
                int kk = kt * 128 + i * 8 + tc * 2;
                if (kk     > r0) s[i][0] = -1e30f;
                if (kk + 1 > r0) s[i][1] = -1e30f;
                if (kk     > r1) s[i][2] = -1e30f;
                if (kk + 1 > r1) s[i][3] = -1e30f;
            }
        }

        float mx0 = -1e30f, mx1 = -1e30f;
        #pragma unroll
        for (int i = 0; i < 16; i++) {
            mx0 = fmaxf(mx0, fmaxf(s[i][0], s[i][1]));
            mx1 = fmaxf(mx1, fmaxf(s[i][2], s[i][3]));
        }
        mx0 = fmaxf(mx0, __shfl_xor_sync(0xffffffffu, mx0, 1));
        mx0 = fmaxf(mx0, __shfl_xor_sync(0xffffffffu, mx0, 2));
        mx1 = fmaxf(mx1, __shfl_xor_sync(0xffffffffu, mx1, 1));
        mx1 = fmaxf(mx1, __shfl_xor_sync(0xffffffffu, mx1, 2));
        float mn0 = fmaxf(mprev0, mx0 * SCALE2), mn1 = fmaxf(mprev1, mx1 * SCALE2);
        float cf0 = ex2f(mprev0 - mn0), cf1 = ex2f(mprev1 - mn1);
        mprev0 = mn0; mprev1 = mn1;

        #pragma unroll
        for (int i = 0; i < 8; i++) {
            oacc[i][0] *= cf0; oacc[i][1] *= cf0;
            oacc[i][2] *= cf1; oacc[i][3] *= cf1;
        }
        sumacc[0] *= cf0; sumacc[1] *= cf0;
        sumacc[2] *= cf1; sumacc[3] *= cf1;

        #pragma unroll
        for (int half = 0; half < 2; half++) {
            uint32_t ph2[8][2];
            #pragma unroll
            for (int ii = 0; ii < 8; ii++) {
                const int i = half * 8 + ii;
                float a0 = fmaf(s[i][0], SCALE2, -mn0);
                float a1 = fmaf(s[i][1], SCALE2, -mn0);
                float a2 = fmaf(s[i][2], SCALE2, -mn1);
                float a3 = fmaf(s[i][3], SCALE2, -mn1);
                ph2[ii][0] = ex2h2(__floats2half2_rn(a0, a1));
                ph2[ii][1] = ex2h2(__floats2half2_rn(a2, a3));
            }
            #pragma unroll
            for (int kgl = 0; kgl < 4; kgl++) {
                const int kg = half * 4 + kgl;
                if (kg < ngmax) {
                    const int h2i = kg >> 2, ks = kg & 3;
                    uint32_t ph[4] = { ph2[2 * kgl][0], ph2[2 * kgl][1],
                                       ph2[2 * kgl + 1][0], ph2[2 * kgl + 1][1] };
                    #pragma unroll
                    for (int ng = 0; ng < 4; ng++) {
                        uint32_t o = sw128((uint32_t)(ng * 16 + frow) * 128 + ks * 32 + fcol)
                                     + h2i * 8192;
                        uint32_t v4[4];
                        ldsm_x4(v4[0], v4[1], v4[2], v4[3], s0 + 16384 + o);
                        #pragma unroll
                        for (int hf = 0; hf < 2; hf++)
                            mma_f16(oacc[ng * 2 + hf], ph, v4[hf], v4[hf + 2]);
                    }
                    mma_f16(sumacc, ph, of[0], of[2]);
                }
            }
        }

        __syncthreads();
        if (kt + 2 < nkt) issueKV(kt + 2);
        cp_commit();
    }

    float sum0 = __shfl_sync(0xffffffffu, sumacc[0], lane & ~3);
    float sum1 = __shfl_sync(0xffffffffu, sumacc[2], lane & ~3);
    float inv0 = 1.f / sum0, inv1 = 1.f / sum1;
    size_t row0 = (size_t)(b * T_SEQ + Q0 + w * 16 + g);
    #pragma unroll
    for (int i = 0; i < 8; i++) {
        int col = h * HDIM + i * 8 + tc * 2;
        *(__half2*)(y + row0 * C_EMB + col) =
            __floats2half2_rn(oacc[i][0] * inv0, oacc[i][1] * inv0);
        *(__half2*)(y + (row0 + 8) * C_EMB + col) =
            __floats2half2_rn(oacc[i][2] * inv1, oacc[i][3] * inv1);
    }
}

// ---------------- launch ----------------
extern "C" void kernel_launch(void* const* d_in, const int* in_sizes, int n_in,
                              void* d_out, int out_size)
{
    const float* x      = (const float*)d_in[0];
    const float* W_attn = (const float*)d_in[1];
    const float* b_attn = (const float*)d_in[2];
    const float* W_proj = (const float*)d_in[3];
    const float* b_proj = (const float*)d_in[4];
    float* out = (float*)d_out;

    __half *qkv, *vt, *a, *bw, *bw2;
    cudaGetSymbolAddress((void**)&qkv, g_qkv);
    cudaGetSymbolAddress((void**)&vt, g_vt);
    cudaGetSymbolAddress((void**)&a, g_a);
    cudaGetSymbolAddress((void**)&bw, g_b);
    cudaGetSymbolAddress((void**)&bw2, g_b2);

    cudaFuncSetAttribute((const void*)gemm_f16<true, true>,
                         cudaFuncAttributeMaxDynamicSharedMemorySize, SM_TOTAL);
    cudaFuncSetAttribute((const void*)gemm_f16<false, false>,
                         cudaFuncAttributeMaxDynamicSharedMemorySize, SM_TOTAL);
    cudaFuncSetAttribute((const void*)attn_f16,
                         cudaFuncAttributeMaxDynamicSharedMemorySize, A_SMEM);

    conv_all<<<4096 + 128 * 32, 256>>>(x, a, W_attn, W_proj, bw, bw2);
    gemm_f16<true, true><<<dim3(C3 / GBN, BT / GBM), 256, SM_TOTAL>>>(
        a, bw, b_attn, nullptr, qkv, vt, BT, C3, C_EMB);
    attn_f16<<<dim3(T_SEQ / 64, NHEAD, BATCH), 128, A_SMEM>>>(qkv, vt, a);
    gemm_f16<false, false><<<dim3(C_EMB / GBN, BT / GBM), 256, SM_TOTAL>>>(
        a, bw2, b_proj, out, nullptr, nullptr, BT, C_EMB, C_EMB);
}

// round 17
// speedup vs baseline: 1.1408x; 1.1274x over previous
#include <cuda_runtime.h>
#include <cuda_fp16.h>
#include <cstdint>

#define BATCH   2
#define T_SEQ   2048
#define C_EMB   1024
#define NHEAD   16
#define HDIM    64
#define BT      (BATCH * T_SEQ)      // 4096
#define C3      (3 * C_EMB)          // 3072

// 0.125 * log2(e)
#define SCALE2  0.18033688011112043f

// ---------------- scratch (device globals) ----------------
__device__ __half g_qkv[(size_t)BT * C3];                       // q,k used; v region unused
__device__ __half g_vt[(size_t)BATCH * NHEAD * HDIM * T_SEQ];   // V^T (written by gemm1)
__device__ __half g_a[(size_t)BT * C_EMB];                      // activation (x, then y)
__device__ __half g_b[(size_t)C3 * C_EMB];                      // W_attn^T fp16
__device__ __half g_b2[(size_t)C_EMB * C_EMB];                  // W_proj^T fp16
__device__ int    g_f2[64];                                     // y row-block ready counters

// ---------------- PTX helpers (base-target sm_80+ only) ----------------
static __device__ __forceinline__ uint32_t smem_u32(const void* p) {
    uint32_t a;
    asm("{ .reg .u64 t; cvta.to.shared.u64 t, %1; cvt.u32.u64 %0, t; }" : "=r"(a) : "l"(p));
    return a;
}
static __device__ __forceinline__ void cp_async16(uint32_t dst, const void* src) {
    asm volatile("cp.async.cg.shared.global [%0], [%1], 16;" :: "r"(dst), "l"(src) : "memory");
}
static __device__ __forceinline__ void cp_commit() {
    asm volatile("cp.async.commit_group;" ::: "memory");
}
static __device__ __forceinline__ void cp_wait1() {
    asm volatile("cp.async.wait_group 1;" ::: "memory");
}
static __device__ __forceinline__ void cp_wait2() {
    asm volatile("cp.async.wait_group 2;" ::: "memory");
}
static __device__ __forceinline__ void ldsm_x4(uint32_t& r0, uint32_t& r1, uint32_t& r2,
                                               uint32_t& r3, uint32_t addr) {
    asm volatile("ldmatrix.sync.aligned.m8n8.x4.shared.b16 {%0,%1,%2,%3}, [%4];"
                 : "=r"(r0), "=r"(r1), "=r"(r2), "=r"(r3) : "r"(addr));
}
static __device__ __forceinline__ void mma_f16(float* d, const uint32_t* a,
                                               uint32_t b0, uint32_t b1) {
    asm volatile(
        "mma.sync.aligned.m16n8k16.row.col.f32.f16.f16.f32 "
        "{%0,%1,%2,%3}, {%4,%5,%6,%7}, {%8,%9}, {%0,%1,%2,%3};"
        : "+f"(d[0]), "+f"(d[1]), "+f"(d[2]), "+f"(d[3])
        : "r"(a[0]), "r"(a[1]), "r"(a[2]), "r"(a[3]), "r"(b0), "r"(b1));
}
static __device__ __forceinline__ float ex2f(float x) {
    float r;
    asm("ex2.approx.f32 %0, %1;" : "=f"(r) : "f"(x));
    return r;
}
static __device__ __forceinline__ uint32_t ex2h2(__half2 x) {
    uint32_t r;
    uint32_t xi = *reinterpret_cast<uint32_t*>(&x);
    asm("ex2.approx.f16x2 %0, %1;" : "=r"(r) : "r"(xi));
    return r;
}
static __device__ __forceinline__ uint32_t sw128(uint32_t o) {
    return o ^ ((o >> 3) & 0x70);
}
static __device__ __forceinline__ void waitf2(int* f, int target) {
    while (atomicAdd(f, 0) < target) __nanosleep(100);
}

// ---------------- HMMA GEMM1: C = A @ B^T + bias (unchanged champion) ----------------
// CTA 128x128, 8 warps (4Mx2N, warp tile 32x64), BK=64, 3-stage, 2 CTAs/SM.
// VSPLIT: N-blocks >= 2*C_EMB (V third) written transposed into vt.
#define GBM 128
#define GBN 128
#define GBK 64
#define G_STG 32768
#define SM_TOTAL (3 * G_STG)

__global__ __launch_bounds__(256, 2)
void gemm1_f16(const __half* __restrict__ A, const __half* __restrict__ B,
               const float* __restrict__ bias,
               __half* __restrict__ Ch, __half* __restrict__ vt,
               int M, int N, int K)
{
    extern __shared__ char smem[];
    const uint32_t sbase = smem_u32(smem);
    const int t = threadIdx.x, lane = t & 31, w = t >> 5;
    const int wm = (w >> 1) * 32;
    const int wn = (w & 1) * 64;
    const int bm = blockIdx.y * GBM, bn = blockIdx.x * GBN;

    const int lr = t >> 3;
    const int lc = (t & 7) * 16;
    const size_t Kb = (size_t)K * 2;
    const char* pA = (const char*)A + (size_t)(bm + lr) * Kb + lc;
    const char* pB = (const char*)B + (size_t)(bn + lr) * Kb + lc;

    auto issue = [&](int c) {
        const uint32_t sb = sbase + (c % 3) * G_STG;
        const size_t go = (size_t)c * 128;
        #pragma unroll
        for (int rr = 0; rr < 4; rr++) {
            uint32_t so = sw128((uint32_t)(lr + rr * 32) * 128 + lc);
            cp_async16(sb + so,         pA + (size_t)rr * 32 * Kb + go);
            cp_async16(sb + 16384 + so, pB + (size_t)rr * 32 * Kb + go);
        }
    };

    float acc[2][8][4] = {};
    const int nc = K / GBK;

    issue(0); cp_commit();
    issue(1); cp_commit();
    issue(2); cp_commit();

    const int frow = lane & 15;
    const int fcol = (lane >> 4) * 16;

    for (int c = 0; c < nc; c++) {
        cp_wait2();
        __syncthreads();
        const uint32_t sb = sbase + (c % 3) * G_STG;

        #pragma unroll
        for (int ks = 0; ks < GBK / 16; ks++) {
            const int kb = ks * 32 + fcol;
            uint32_t af[2][4];
            #pragma unroll
            for (int mt = 0; mt < 2; mt++) {
                uint32_t o = sw128((uint32_t)(wm + mt * 16 + frow) * 128 + kb);
                ldsm_x4(af[mt][0], af[mt][1], af[mt][2], af[mt][3], sb + o);
            }
            uint32_t bf[4][4];
            #pragma unroll
            for (int nt = 0; nt < 4; nt++) {
                uint32_t o = sw128((uint32_t)(wn + nt * 16 + frow) * 128 + kb);
                ldsm_x4(bf[nt][0], bf[nt][1], bf[nt][2], bf[nt][3], sb + 16384 + o);
            }
            #pragma unroll
            for (int nt = 0; nt < 4; nt++)
                #pragma unroll
                for (int mt = 0; mt < 2; mt++)
                    #pragma unroll
                    for (int hf = 0; hf < 2; hf++)
                        mma_f16(acc[mt][nt * 2 + hf], af[mt], bf[nt][hf], bf[nt][hf + 2]);
        }
        __syncthreads();
        if (c + 3 < nc) issue(c + 3);
        cp_commit();
    }

    const int g = lane >> 2, tc = lane & 3;
    const bool isV = (bn >= 2 * C_EMB);
    #pragma unroll
    for (int mt = 0; mt < 2; mt++) {
        const int row0 = bm + wm + mt * 16 + g;
        #pragma unroll
        for (int j = 0; j < 8; j++) {
            const int col = bn + wn + j * 8 + tc * 2;
            float b0 = bias[col], b1 = bias[col + 1];
            float* d = acc[mt][j];
            float v00 = d[0] + b0, v01 = d[1] + b1;
            float v10 = d[2] + b0, v11 = d[3] + b1;
            if (isV) {
                const int vcol = col - 2 * C_EMB;
                const int hh = vcol >> 6, dd = vcol & 63;
                const int bb = row0 >> 11, tt = row0 & 2047;
                size_t base = ((size_t)(bb * NHEAD + hh) * HDIM + dd) * T_SEQ + tt;
                vt[base]             = __float2half(v00);
                vt[base + T_SEQ]     = __float2half(v01);
                vt[base + 8]         = __float2half(v10);
                vt[base + T_SEQ + 8] = __float2half(v11);
            } else {
                *(__half2*)(Ch + (size_t)row0 * N + col) = __floats2half2_rn(v00, v01);
                *(__half2*)(Ch + (size_t)(row0 + 8) * N + col) = __floats2half2_rn(v10, v11);
            }
        }
    }
}

// ---------------- merged conversion kernel (+ flag reset) ----------------
__global__ void conv_all(const float* __restrict__ x, __half* __restrict__ a,
                         const float* __restrict__ Wa, const float* __restrict__ Wp,
                         __half* __restrict__ ba, __half* __restrict__ bp)
{
    __shared__ float tile[32][33];
    const int t = threadIdx.x;
    if (blockIdx.x == 0 && t < 64) g_f2[t] = 0;   // reset flags each replay
    if (blockIdx.x < 4096) {
        int i = (blockIdx.x * 256 + t) * 4;
        float4 v = *(const float4*)(x + i);
        *(__half2*)(a + i)     = __floats2half2_rn(v.x, v.y);
        *(__half2*)(a + i + 2) = __floats2half2_rn(v.z, v.w);
        return;
    }
    const int bid = blockIdx.x - 4096;
    const int bxT = bid & 127;
    const int k0  = (bid >> 7) * 32;
    const float* W;
    __half* outp;
    int N, n0;
    if (bxT < 96) { W = Wa; outp = ba; N = C3;    n0 = bxT * 32; }
    else          { W = Wp; outp = bp; N = C_EMB; n0 = (bxT - 96) * 32; }
    const int tx = t & 31, ty = t >> 5;
    #pragma unroll
    for (int j = 0; j < 32; j += 8)
        tile[ty + j][tx] = W[(size_t)(k0 + ty + j) * N + n0 + tx];
    __syncthreads();
    #pragma unroll
    for (int j = 0; j < 32; j += 8)
        outp[(size_t)(n0 + ty + j) * C_EMB + k0 + tx] = __float2half(tile[tx][ty + j]);
}

// ---------------- merged attention + output-projection kernel ----------------
// bids [0,1024):  flash attention (champion body), sets g_f2 row-block counters.
// bids [1024,1536): gemm2 64x128 tiles (4 warps), spins on g_f2[mb]==16.
#define A_SQ   0
#define A_ONES 8192
#define A_SK   10240
#define A_STG  32768
#define A_SMEM (A_SK + 2 * A_STG)   // 75776 -> 3 CTAs/SM

#define P_STG  24576                 // A 8K | B 16K per stage; 3 stages = 73728

__global__ __launch_bounds__(128, 3)
void attn_proj(const __half* __restrict__ qkv, const __half* __restrict__ vt,
               __half* __restrict__ y,
               const __half* __restrict__ Wp, const float* __restrict__ bproj,
               float* __restrict__ out)
{
    extern __shared__ char smem[];
    const uint32_t sb = smem_u32(smem);
    const int t = threadIdx.x, lane = t & 31, w = t >> 5;

    if (blockIdx.x >= 1024) {
        // ================= gemm2: out = y @ Wp^T + bproj =================
        const int gid = blockIdx.x - 1024;
        const int qb2 = 31 - (gid >> 4);
        const int bsel = (gid >> 3) & 1;
        const int mb = bsel * 32 + qb2;          // heavy rows ready first
        const int bm = mb * 64;
        const int bn = (gid & 7) * 128;

        if (t == 0) waitf2(&g_f2[mb], 16);
        __syncthreads();

        const int wm = (w >> 1) * 32;
        const int wn = (w & 1) * 64;
        const int lr = t >> 3;
        const int lc = (t & 7) * 16;
        const size_t Kb = (size_t)C_EMB * 2;
        const char* pA = (const char*)y  + (size_t)(bm + lr) * Kb + lc;
        const char* pB = (const char*)Wp + (size_t)(bn + lr) * Kb + lc;

        auto issue = [&](int c) {
            const uint32_t s0 = sb + (c % 3) * P_STG;
            const size_t go = (size_t)c * 128;
            #pragma unroll
            for (int rr = 0; rr < 4; rr++) {
                uint32_t so = sw128((uint32_t)(lr + rr * 16) * 128 + lc);
                cp_async16(s0 + so, pA + (size_t)rr * 16 * Kb + go);
            }
            #pragma unroll
            for (int rr = 0; rr < 8; rr++) {
                uint32_t so = sw128((uint32_t)(lr + rr * 16) * 128 + lc);
                cp_async16(s0 + 8192 + so, pB + (size_t)rr * 16 * Kb + go);
            }
        };

        float acc[2][8][4] = {};
        const int nc = C_EMB / GBK;   // 16

        issue(0); cp_commit();
        issue(1); cp_commit();
        issue(2); cp_commit();

        const int frow = lane & 15;
        const int fcol = (lane >> 4) * 16;

        for (int c = 0; c < nc; c++) {
            cp_wait2();
            __syncthreads();
            const uint32_t s0 = sb + (c % 3) * P_STG;

            #pragma unroll
            for (int ks = 0; ks < GBK / 16; ks++) {
                const int kb = ks * 32 + fcol;
                uint32_t af[2][4];
                #pragma unroll
                for (int mt = 0; mt < 2; mt++) {
                    uint32_t o = sw128((uint32_t)(wm + mt * 16 + frow) * 128 + kb);
                    ldsm_x4(af[mt][0], af[mt][1], af[mt][2], af[mt][3], s0 + o);
                }
                uint32_t bf[4][4];
                #pragma unroll
                for (int nt = 0; nt < 4; nt++) {
                    uint32_t o = sw128((uint32_t)(wn + nt * 16 + frow) * 128 + kb);
                    ldsm_x4(bf[nt][0], bf[nt][1], bf[nt][2], bf[nt][3], s0 + 8192 + o);
                }
                #pragma unroll
                for (int nt = 0; nt < 4; nt++)
                    #pragma unroll
                    for (int mt = 0; mt < 2; mt++)
                        #pragma unroll
                        for (int hf = 0; hf < 2; hf++)
                            mma_f16(acc[mt][nt * 2 + hf], af[mt], bf[nt][hf], bf[nt][hf + 2]);
            }
            __syncthreads();
            if (c + 3 < nc) issue(c + 3);
            cp_commit();
        }

        const int g = lane >> 2, tc = lane & 3;
        #pragma unroll
        for (int mt = 0; mt < 2; mt++) {
            const int row0 = bm + wm + mt * 16 + g;
            #pragma unroll
            for (int j = 0; j < 8; j++) {
                const int col = bn + wn + j * 8 + tc * 2;
                float b0 = bproj[col], b1 = bproj[col + 1];
                float* d = acc[mt][j];
                *(float2*)(out + (size_t)row0 * C_EMB + col) =
                    make_float2(d[0] + b0, d[1] + b1);
                *(float2*)(out + (size_t)(row0 + 8) * C_EMB + col) =
                    make_float2(d[2] + b0, d[3] + b1);
            }
        }
        return;
    }

    // ================= flash attention (champion body) =================
    const int aid = blockIdx.x;
    const int qb = 31 - (aid >> 5);              // heavy blocks first
    const int h = aid & 15, b = (aid >> 4) & 1;
    const int Q0 = qb * 64;
    const int nkt = (Q0 >> 7) + 1;

    const int lr = t >> 3;
    const int lc = (t & 7) * 16;
    const char* qb8 = (const char*)qkv;
    const char* vb8 = (const char*)vt;

    {
        uint32_t v = (t < 8) ? 0x3C003C00u : 0u;
        *(uint4*)(smem + A_ONES + t * 16) = make_uint4(v, v, v, v);
    }

    auto issueQ = [&]() {
        #pragma unroll
        for (int rr = 0; rr < 4; rr++) {
            int row = lr + rr * 16;
            size_t g = ((size_t)(b * T_SEQ + Q0 + row) * C3 + h * HDIM) * 2 + lc;
            cp_async16(sb + A_SQ + sw128((uint32_t)row * 128 + lc), qb8 + g);
        }
    };
    auto issueKV = [&](int kt) {
        uint32_t s0 = sb + A_SK + (kt & 1) * A_STG;
        #pragma unroll
        for (int rr = 0; rr < 8; rr++) {
            int row = lr + rr * 16;
            uint32_t so = sw128((uint32_t)row * 128 + lc);
            size_t gk = ((size_t)(b * T_SEQ + kt * 128 + row) * C3 + C_EMB + h * HDIM) * 2 + lc;
            cp_async16(s0 + so, qb8 + gk);
        }
        #pragma unroll
        for (int j = 0; j < 2; j++) {
            #pragma unroll
            for (int rr = 0; rr < 4; rr++) {
                int row = lr + rr * 16;
                uint32_t so = sw128((uint32_t)row * 128 + lc) + j * 8192;
                size_t gv = (((size_t)(b * NHEAD + h) * HDIM + row) * T_SEQ
                             + kt * 128 + j * 64) * 2 + lc;
                cp_async16(s0 + 16384 + so, vb8 + gv);
            }
        }
    };

    issueQ(); issueKV(0); cp_commit();
    if (nkt > 1) issueKV(1);
    cp_commit();

    const int frow = lane & 15;
    const int fcol = (lane >> 4) * 16;
    const int g = lane >> 2, tc = lane & 3;

    cp_wait1();
    __syncthreads();

    uint32_t qf[4][4];
    #pragma unroll
    for (int ks = 0; ks < 4; ks++) {
        uint32_t o = sw128((uint32_t)(w * 16 + frow) * 128 + ks * 32 + fcol);
        ldsm_x4(qf[ks][0], qf[ks][1], qf[ks][2], qf[ks][3], sb + A_SQ + o);
    }
    uint32_t of[4];
    ldsm_x4(of[0], of[1], of[2], of[3], sb + A_ONES + sw128((uint32_t)frow * 128 + fcol));

    float oacc[8][4] = {};
    float sumacc[4] = {};
    float mprev0 = -1e30f, mprev1 = -1e30f;
    const int r0 = Q0 + w * 16 + g;
    const int r1 = r0 + 8;

    for (int kt = 0; kt < nkt; kt++) {
        if (kt > 0) { cp_wait1(); __syncthreads(); }
        const uint32_t s0 = sb + A_SK + (kt & 1) * A_STG;
        const bool diag = (kt == nkt - 1);
        int ngmax = 8;
        if (diag) {
            ngmax = ((Q0 & 127) >> 4) + w + 1;
            if (ngmax > 8) ngmax = 8;
        }

        float s[16][4] = {};
        #pragma unroll
        for (int ng = 0; ng < 8; ng++) {
            if (ng < ngmax) {
                #pragma unroll
                for (int ks = 0; ks < 4; ks++) {
                    uint32_t o = sw128((uint32_t)(ng * 16 + frow) * 128 + ks * 32 + fcol);
                    uint32_t kh[4];
                    ldsm_x4(kh[0], kh[1], kh[2], kh[3], s0 + o);
                    #pragma unroll
                    for (int hf = 0; hf < 2; hf++)
                        mma_f16(s[ng * 2 + hf], qf[ks], kh[hf], kh[hf + 2]);
                }
            }
        }

        if (diag) {
            #pragma unroll
            for (int i = 0; i < 16; i++) {
                int kk = kt * 128 + i * 8 + tc * 2;
                if (kk     > r0) s[i][0] = -1e30f;
                if (kk + 1 > r0) s[i][1] = -1e30f;
                if (kk     > r1) s[i][2] = -1e30f;
                if (kk + 1 > r1) s[i][3] = -1e30f;
            }
        }

        float mx0 = -1e30f, mx1 = -1e30f;
        #pragma unroll
        for (int i = 0; i < 16; i++) {
            mx0 = fmaxf(mx0, fmaxf(s[i][0], s[i][1]));
            mx1 = fmaxf(mx1, fmaxf(s[i][2], s[i][3]));
        }
        mx0 = fmaxf(mx0, __shfl_xor_sync(0xffffffffu, mx0, 1));
        mx0 = fmaxf(mx0, __shfl_xor_sync(0xffffffffu, mx0, 2));
        mx1 = fmaxf(mx1, __shfl_xor_sync(0xffffffffu, mx1, 1));
        mx1 = fmaxf(mx1, __shfl_xor_sync(0xffffffffu, mx1, 2));
        float mn0 = fmaxf(mprev0, mx0 * SCALE2), mn1 = fmaxf(mprev1, mx1 * SCALE2);
        float cf0 = ex2f(mprev0 - mn0), cf1 = ex2f(mprev1 - mn1);
        mprev0 = mn0; mprev1 = mn1;

        #pragma unroll
        for (int i = 0; i < 8; i++) {
            oacc[i][0] *= cf0; oacc[i][1] *= cf0;
            oacc[i][2] *= cf1; oacc[i][3] *= cf1;
        }
        sumacc[0] *= cf0; sumacc[1] *= cf0;
        sumacc[2] *= cf1; sumacc[3] *= cf1;

        #pragma unroll
        for (int half = 0; half < 2; half++) {
            uint32_t ph2[8][2];
            #pragma unroll
            for (int ii = 0; ii < 8; ii++) {
                const int i = half * 8 + ii;
                float a0 = fmaf(s[i][0], SCALE2, -mn0);
                float a1 = fmaf(s[i][1], SCALE2, -mn0);
                float a2 = fmaf(s[i][2], SCALE2, -mn1);
                float a3 = fmaf(s[i][3], SCALE2, -mn1);
                ph2[ii][0] = ex2h2(__floats2half2_rn(a0, a1));
                ph2[ii][1] = ex2h2(__floats2half2_rn(a2, a3));
            }
            #pragma unroll
            for (int kgl = 0; kgl < 4; kgl++) {
                const int kg = half * 4 + kgl;
                if (kg < ngmax) {
                    const int h2i = kg >> 2, ks = kg & 3;
                    uint32_t ph[4] = { ph2[2 * kgl][0], ph2[2 * kgl][1],
                                       ph2[2 * kgl + 1][0], ph2[2 * kgl + 1][1] };
                    #pragma unroll
                    for (int ng = 0; ng < 4; ng++) {
                        uint32_t o = sw128((uint32_t)(ng * 16 + frow) * 128 + ks * 32 + fcol)
                                     + h2i * 8192;
                        uint32_t v4[4];
                        ldsm_x4(v4[0], v4[1], v4[2], v4[3], s0 + 16384 + o);
                        #pragma unroll
                        for (int hf = 0; hf < 2; hf++)
                            mma_f16(oacc[ng * 2 + hf], ph, v4[hf], v4[hf + 2]);
                    }
                    mma_f16(sumacc, ph, of[0], of[2]);
                }
            }
        }

        __syncthreads();
        if (kt + 2 < nkt) issueKV(kt + 2);
        cp_commit();
    }

    float sum0 = __shfl_sync(0xffffffffu, sumacc[0], lane & ~3);
    float sum1 = __shfl_sync(0xffffffffu, sumacc[2], lane & ~3);
    float inv0 = 1.f / sum0, inv1 = 1.f / sum1;
    size_t row0 = (size_t)(b * T_SEQ + Q0 + w * 16 + g);
    #pragma unroll
    for (int i = 0; i < 8; i++) {
        int col = h * HDIM + i * 8 + tc * 2;
        *(__half2*)(y + row0 * C_EMB + col) =
            __floats2half2_rn(oacc[i][0] * inv0, oacc[i][1] * inv0);
        *(__half2*)(y + (row0 + 8) * C_EMB + col) =
            __floats2half2_rn(oacc[i][2] * inv1, oacc[i][3] * inv1);
    }

    // publish: y row-block (b, qb) contribution from this head is done
    __threadfence();
    __syncthreads();
    if (t == 0) atomicAdd(&g_f2[b * 32 + qb], 1);
}

// ---------------- launch ----------------
extern "C" void kernel_launch(void* const* d_in, const int* in_sizes, int n_in,
                              void* d_out, int out_size)
{
    const float* x      = (const float*)d_in[0];
    const float* W_attn = (const float*)d_in[1];
    const float* b_attn = (const float*)d_in[2];
    const float* W_proj = (const float*)d_in[3];
    const float* b_proj = (const float*)d_in[4];
    float* out = (float*)d_out;

    __half *qkv, *vt, *a, *bw, *bw2;
    cudaGetSymbolAddress((void**)&qkv, g_qkv);
    cudaGetSymbolAddress((void**)&vt, g_vt);
    cudaGetSymbolAddress((void**)&a, g_a);
    cudaGetSymbolAddress((void**)&bw, g_b);
    cudaGetSymbolAddress((void**)&bw2, g_b2);

    cudaFuncSetAttribute((const void*)gemm1_f16,
                         cudaFuncAttributeMaxDynamicSharedMemorySize, SM_TOTAL);
    cudaFuncSetAttribute((const void*)attn_proj,
                         cudaFuncAttributeMaxDynamicSharedMemorySize, A_SMEM);

    // 1) x->fp16 + both weight transposes + flag reset
    conv_all<<<4096 + 128 * 32, 256>>>(x, a, W_attn, W_proj, bw, bw2);
    // 2) qkv = x @ W_attn + b_attn; V third written transposed into vt
    gemm1_f16<<<dim3(C3 / GBN, BT / GBM), 256, SM_TOTAL>>>(
        a, bw, b_attn, qkv, vt, BT, C3, C_EMB);
    // 3) attention + output projection, overlapped via row-block flags
    attn_proj<<<1024 + 512, 128, A_SMEM>>>(qkv, vt, a, bw2, b_proj, out);
}